// round 10
// baseline (speedup 1.0000x reference)
#include <cuda_runtime.h>
#include <math.h>

#define EPSF 1e-8f
#define NB 3
#define NF 1024
#define NP 768
#define IMG 128
#define NPIX (IMG * IMG)

#define GRID_BLOCKS 384
#define BLOCK_THREADS 256

// out offsets (f32 elements)
#define OFF_IM     0
#define OFF_PROB   49152
#define OFF_NORM   65536
#define OFF_FG     74752

// Inverted-key z-buffer: 0 = empty (module-load default & post-shade state).
// key = (~bits(z))<<32 | (1023-f)<<18 | tyi<<9 | txi
//   atomicMax => min z; z-tie -> min face; texel bits never affect order.
static __device__ unsigned long long g_zbuf[NB * NPIX];
// Monotone epoch barrier counter (never reset; epoch = value / gridDim).
static __device__ unsigned long long g_bar;

__device__ __forceinline__ float pix_x(int x) {
    const float STEP = 2.0f / 127.0f;
    return (x == 127) ? 1.0f : (-1.0f + x * STEP);
}
__device__ __forceinline__ float pix_y(int y) {
    const float STEP = 2.0f / 127.0f;
    return (y == 127) ? -1.0f : (1.0f - y * STEP);
}

// ---------------------------------------------------------------------------
// Single fused kernel: prep + scatter | grid barrier | shade.
// 384 blocks x 256 threads; one warp per (layer, face) in phase 1; first
// 16384 threads shade one pixel each in phase 2.
// ---------------------------------------------------------------------------
__global__ void __launch_bounds__(BLOCK_THREADS)
render_kernel(const float* __restrict__ pts,
              const float* __restrict__ camrot,
              const float* __restrict__ campos,
              const float* __restrict__ proj,
              const int*   __restrict__ faces,
              const float* __restrict__ uv,
              const float* __restrict__ ts,
              const float* __restrict__ tex,
              float* __restrict__ out) {
    int gtid = blockIdx.x * BLOCK_THREADS + threadIdx.x;
    int wg = gtid >> 5;
    int lane = threadIdx.x & 31;

    // ===================== Phase 1: prep + scatter =====================
    {
        int l = wg >> 10;
        int f = wg & (NF - 1);

        int vis[3] = {faces[f * 3 + 0], faces[f * 3 + 1], faces[f * 3 + 2]};
        const float* R = camrot + l * 9;
        const float* C = campos + l * 3;
        float p0 = proj[0], p1 = proj[1];

        float vx[3], vy[3], vz[3], sx[3], sy[3];
#pragma unroll
        for (int k = 0; k < 3; k++) {
            const float* P = pts + (l * NP + vis[k]) * 3;
            float q0 = P[0] - C[0], q1 = P[1] - C[1], q2 = P[2] - C[2];
            float X = R[0] * q0 + R[1] * q1 + R[2] * q2;
            float Y = R[3] * q0 + R[4] * q1 + R[5] * q2;
            float Z = R[6] * q0 + R[7] * q1 + R[8] * q2;
            vx[k] = X; vy[k] = Y; vz[k] = Z;
            float zd = Z + EPSF;
            sx[k] = __fdiv_rn(X * p0, zd);
            sy[k] = __fdiv_rn(Y * p1, zd);
        }

        if (lane == 0) {
            float e1xx = vx[1] - vx[0], e1yy = vy[1] - vy[0], e1zz = vz[1] - vz[0];
            float e2xx = vx[2] - vx[0], e2yy = vy[2] - vy[0], e2zz = vz[2] - vz[0];
            float nx = e1yy * e2zz - e1zz * e2yy;
            float ny = e1zz * e2xx - e1xx * e2zz;
            float nz = e1xx * e2yy - e1yy * e2xx;
            float nn = __fsqrt_rn(nx * nx + ny * ny + nz * nz) + EPSF;
            float* on = out + OFF_NORM + wg * 3;
            on[0] = __fdiv_rn(nx, nn);
            on[1] = __fdiv_rn(ny, nn);
            on[2] = __fdiv_rn(nz, nn);
        }

        float ax = sx[0], ay = sy[0], bx = sx[1], by = sy[1], cx = sx[2], cy = sy[2];
        float d = (by - cy) * (ax - cx) + (cx - bx) * (ay - cy);
        float zmax = fmaxf(vz[0], fmaxf(vz[1], vz[2]));
        bool valid = (fabsf(d) > EPSF) && (zmax > EPSF);

        if (valid) {
            float dn = d + EPSF;
            float rd = __frcp_rn(dn);
            float4 A = make_float4(by - cy, cx - bx, cy - ay, ax - cx);
            float4 B = make_float4(cx, cy, rd, vz[0]);
            float z1v = vz[1], z2v = vz[2];

            const float* U = uv + l * NP * 2;
            float u0 = U[2 * vis[0]],     u1 = U[2 * vis[1]],     u2 = U[2 * vis[2]];
            float v0 = U[2 * vis[0] + 1], v1 = U[2 * vis[1] + 1], v2 = U[2 * vis[2] + 1];

            const float STEP = 2.0f / 127.0f;
            float pad = 1.0f * STEP;
            float xmin = fminf(ax, fminf(bx, cx)) - pad;
            float xmax = fmaxf(ax, fmaxf(bx, cx)) + pad;
            float ymin = fminf(ay, fminf(by, cy)) - pad;
            float ymax = fmaxf(ay, fmaxf(by, cy)) + pad;

            const float INV_STEP = 63.5f;   // 1 / (2/127)
            int x0 = max(0, (int)floorf((xmin + 1.0f) * INV_STEP));
            int x1 = min(IMG - 1, (int)ceilf((xmax + 1.0f) * INV_STEP));
            int y0 = max(0, (int)floorf((1.0f - ymax) * INV_STEP));
            int y1 = min(IMG - 1, (int)ceilf((1.0f - ymin) * INV_STEP));

            if (x0 <= x1 && y0 <= y1) {
                int w = x1 - x0 + 1;
                int total = w * (y1 - y0 + 1);
                unsigned long long* zb = g_zbuf + l * NPIX;
                unsigned invf = 1023u - (unsigned)f;

                for (int i = lane; i < total; i += 32) {
                    int yy = y0 + i / w;
                    int xx = x0 + i % w;
                    float px = pix_x(xx), py = pix_y(yy);
                    float dx = px - B.x, dy = py - B.y;
                    float l0 = (A.x * dx + A.y * dy) * B.z;
                    float l1 = (A.z * dx + A.w * dy) * B.z;
                    float l2 = 1.0f - l0 - l1;
                    float z  = l0 * B.w + l1 * z1v + l2 * z2v;
                    if (l0 >= 0.0f && l1 >= 0.0f && l2 >= 0.0f && z > EPSF) {
                        float u = l0 * u0 + l1 * u1 + l2 * u2;
                        float v = l0 * v0 + l1 * v1 + l2 * v2;
                        u = fminf(fmaxf(u, 0.0f), 1.0f);
                        v = fminf(fmaxf(v, 0.0f), 1.0f);
                        unsigned txi = (unsigned)(int)rintf(u * 511.0f);
                        unsigned tyi = (unsigned)(int)rintf((1.0f - v) * 511.0f);
                        unsigned long long key =
                            ((unsigned long long)(~__float_as_uint(z)) << 32)
                            | (invf << 18) | (tyi << 9) | txi;
                        atomicMax(&zb[yy * IMG + xx], key);
                    }
                }
            }
        }
    }

    // ===================== Grid barrier (epoch, monotone) =====================
    __syncthreads();
    if (threadIdx.x == 0) {
        __threadfence();
        unsigned long long v = atomicAdd(&g_bar, 1ull);
        unsigned long long G = (unsigned long long)gridDim.x;
        unsigned long long target = (v / G + 1ull) * G;
        while (true) {
            unsigned long long cur;
            asm volatile("ld.volatile.global.u64 %0, [%1];"
                         : "=l"(cur) : "l"(&g_bar));
            if (cur >= target) break;
            __nanosleep(64);
        }
    }
    __syncthreads();
    __threadfence();

    // ===================== Phase 2: shade =====================
    int pid = gtid;
    if (pid >= NPIX) return;

    unsigned long long k0v = g_zbuf[0 * NPIX + pid];
    unsigned long long k1v = g_zbuf[1 * NPIX + pid];
    unsigned long long k2v = g_zbuf[2 * NPIX + pid];
    g_zbuf[0 * NPIX + pid] = 0ull;
    g_zbuf[1 * NPIX + pid] = 0ull;
    g_zbuf[2 * NPIX + pid] = 0ull;
    unsigned long long keys[3] = {k0v, k1v, k2v};

    // stable argsort of -ts[:,2]
    float k0 = -ts[2], k1 = -ts[5], k2 = -ts[8];
    int o0 = 0; float kv = k0;
    if (k1 < kv) { o0 = 1; kv = k1; }
    if (k2 < kv) { o0 = 2; kv = k2; }
    int r0i = (o0 == 0) ? 1 : 0;
    int r1i = (o0 == 2) ? 1 : 2;
    float kr0 = (r0i == 0) ? k0 : k1;
    float kr1 = (r1i == 1) ? k1 : k2;
    int o1, o2;
    if (kr0 <= kr1) { o1 = r0i; o2 = r1i; }
    else            { o1 = r1i; o2 = r0i; }

    unsigned long long ksel = keys[o0];
    int sel = o0;
    if (keys[o1] != 0ull) { sel = o1; ksel = keys[o1]; }
    if (keys[o2] != 0ull) { sel = o2; ksel = keys[o2]; }

    float c0 = 0.0f, c1 = 0.0f, c2 = 0.0f, hard = 0.0f;
    if (ksel != 0ull) {
        hard = 1.0f;
        unsigned lo = (unsigned)(ksel & 0xFFFFFFFFull);
        int txi = lo & 511;
        int tyi = (lo >> 9) & 511;
        const float* T = tex + sel * 3 * 512 * 512 + tyi * 512 + txi;
        c0 = T[0];
        c1 = T[262144];
        c2 = T[524288];
    }

    out[OFF_IM + pid * 3 + 0] = c0;
    out[OFF_IM + pid * 3 + 1] = c1;
    out[OFF_IM + pid * 3 + 2] = c2;
    out[OFF_PROB + pid] = hard;
    out[OFF_FG + pid]   = hard;
}

// ---------------------------------------------------------------------------
extern "C" void kernel_launch(void* const* d_in, const int* in_sizes, int n_in,
                              void* d_out, int out_size) {
    const float* points = (const float*)d_in[0];
    const float* camrot = (const float*)d_in[1];
    const float* campos = (const float*)d_in[2];
    const float* proj   = (const float*)d_in[3];
    const float* uv     = (const float*)d_in[4];
    const float* tex    = (const float*)d_in[5];
    const float* ts     = (const float*)d_in[6];
    const int*   faces  = (const int*)d_in[7];
    float* out = (float*)d_out;

    render_kernel<<<GRID_BLOCKS, BLOCK_THREADS>>>(points, camrot, campos, proj,
                                                  faces, uv, ts, tex, out);
}

// round 11
// speedup vs baseline: 1.4510x; 1.4510x over previous
#include <cuda_runtime.h>
#include <math.h>

#define EPSF 1e-8f
#define NB 3
#define NF 1024
#define NP 768
#define IMG 128
#define NPIX (IMG * IMG)

// out offsets (f32 elements)
#define OFF_IM     0
#define OFF_PROB   49152
#define OFF_NORM   65536
#define OFF_FG     74752

// Combined composite/z buffer, one u64 per pixel. 0 = empty (module-load
// default, restored by shade each call).
// key = rank<<62 | (~bits(z))<<30 | (1023-f)<<20 | layer<<18 | tyi<<9 | txi
//   atomicMax => max composite rank (last-drawn layer in ts order);
//   within a layer: min z, tie -> min face. Texel bits never affect order
//   (equal (layer,z,f,pixel) => equal texel coords).
static __device__ unsigned long long g_zbuf[NPIX];

__device__ __forceinline__ float pix_x(int x) {
    const float STEP = 2.0f / 127.0f;
    return (x == 127) ? 1.0f : (-1.0f + x * STEP);
}
__device__ __forceinline__ float pix_y(int y) {
    const float STEP = 2.0f / 127.0f;
    return (y == 127) ? -1.0f : (1.0f - y * STEP);
}

// stable argsort of -ts[:,2] over 3 layers; returns rank of layer l (0..2)
__device__ __forceinline__ int layer_rank(const float* ts, int l) {
    float k0 = -ts[2], k1 = -ts[5], k2 = -ts[8];
    int o0 = 0; float kv = k0;
    if (k1 < kv) { o0 = 1; kv = k1; }
    if (k2 < kv) { o0 = 2; kv = k2; }
    int r0i = (o0 == 0) ? 1 : 0;
    int r1i = (o0 == 2) ? 1 : 2;
    float kr0 = (r0i == 0) ? k0 : k1;
    float kr1 = (r1i == 1) ? k1 : k2;
    int o1, o2;
    if (kr0 <= kr1) { o1 = r0i; o2 = r1i; }
    else            { o1 = r1i; o2 = r0i; }
    return (l == o0) ? 0 : ((l == o1) ? 1 : 2);
}

// ---------------------------------------------------------------------------
// Kernel 1: prep + scatter. TWO warps per (layer, face) — interleaved halves
// of the flattened bbox sweep — to halve the big-bbox tail.
// ---------------------------------------------------------------------------
__global__ void __launch_bounds__(256)
scatter_kernel(const float* __restrict__ pts,
               const float* __restrict__ camrot,
               const float* __restrict__ campos,
               const float* __restrict__ proj,
               const int*   __restrict__ faces,
               const float* __restrict__ uv,
               const float* __restrict__ ts,
               float* __restrict__ out_normals) {
    int w = (blockIdx.x * blockDim.x + threadIdx.x) >> 5;   // 0 .. 6143
    int lane = threadIdx.x & 31;
    int wg = w >> 1;            // (layer, face) id
    int half = w & 1;
    if (wg >= NB * NF) return;
    int l = wg >> 10;
    int f = wg & (NF - 1);

    int vis[3] = {faces[f * 3 + 0], faces[f * 3 + 1], faces[f * 3 + 2]};
    const float* R = camrot + l * 9;
    const float* C = campos + l * 3;
    float p0 = proj[0], p1 = proj[1];

    float vx[3], vy[3], vz[3], sx[3], sy[3];
#pragma unroll
    for (int k = 0; k < 3; k++) {
        const float* P = pts + (l * NP + vis[k]) * 3;
        float q0 = P[0] - C[0], q1 = P[1] - C[1], q2 = P[2] - C[2];
        float X = R[0] * q0 + R[1] * q1 + R[2] * q2;
        float Y = R[3] * q0 + R[4] * q1 + R[5] * q2;
        float Z = R[6] * q0 + R[7] * q1 + R[8] * q2;
        vx[k] = X; vy[k] = Y; vz[k] = Z;
        float zd = Z + EPSF;
        sx[k] = __fdiv_rn(X * p0, zd);
        sy[k] = __fdiv_rn(Y * p1, zd);
    }

    if (lane == 0 && half == 0) {
        float e1xx = vx[1] - vx[0], e1yy = vy[1] - vy[0], e1zz = vz[1] - vz[0];
        float e2xx = vx[2] - vx[0], e2yy = vy[2] - vy[0], e2zz = vz[2] - vz[0];
        float nx = e1yy * e2zz - e1zz * e2yy;
        float ny = e1zz * e2xx - e1xx * e2zz;
        float nz = e1xx * e2yy - e1yy * e2xx;
        float nn = __fsqrt_rn(nx * nx + ny * ny + nz * nz) + EPSF;
        float* on = out_normals + wg * 3;
        on[0] = __fdiv_rn(nx, nn);
        on[1] = __fdiv_rn(ny, nn);
        on[2] = __fdiv_rn(nz, nn);
    }

    float ax = sx[0], ay = sy[0], bx = sx[1], by = sy[1], cx = sx[2], cy = sy[2];
    float d = (by - cy) * (ax - cx) + (cx - bx) * (ay - cy);
    float zmax = fmaxf(vz[0], fmaxf(vz[1], vz[2]));
    bool valid = (fabsf(d) > EPSF) && (zmax > EPSF);
    if (!valid) return;

    float dn = d + EPSF;
    float rd = __frcp_rn(dn);
    float4 A = make_float4(by - cy, cx - bx, cy - ay, ax - cx);
    float4 B = make_float4(cx, cy, rd, vz[0]);
    float z1v = vz[1], z2v = vz[2];

    const float* U = uv + l * NP * 2;
    float u0 = U[2 * vis[0]],     u1 = U[2 * vis[1]],     u2 = U[2 * vis[2]];
    float v0 = U[2 * vis[0] + 1], v1 = U[2 * vis[1] + 1], v2 = U[2 * vis[2] + 1];

    const float STEP = 2.0f / 127.0f;
    float pad = 1.0f * STEP;
    float xmin = fminf(ax, fminf(bx, cx)) - pad;
    float xmax = fmaxf(ax, fmaxf(bx, cx)) + pad;
    float ymin = fminf(ay, fminf(by, cy)) - pad;
    float ymax = fmaxf(ay, fmaxf(by, cy)) + pad;

    const float INV_STEP = 63.5f;       // 1 / (2/127)
    int x0 = max(0, (int)floorf((xmin + 1.0f) * INV_STEP));
    int x1 = min(IMG - 1, (int)ceilf((xmax + 1.0f) * INV_STEP));
    int y0 = max(0, (int)floorf((1.0f - ymax) * INV_STEP));
    int y1 = min(IMG - 1, (int)ceilf((1.0f - ymin) * INV_STEP));
    if (x0 > x1 || y0 > y1) return;

    int wdt = x1 - x0 + 1;
    int total = wdt * (y1 - y0 + 1);

    unsigned long long rank = (unsigned long long)layer_rank(ts, l);
    unsigned long long tagbits = (rank << 62)
        | ((unsigned long long)(1023u - (unsigned)f) << 20)
        | ((unsigned long long)l << 18);

    for (int i = half * 32 + lane; i < total; i += 64) {
        int yy = y0 + i / wdt;
        int xx = x0 + i % wdt;
        float px = pix_x(xx), py = pix_y(yy);
        float dx = px - B.x, dy = py - B.y;
        float l0 = (A.x * dx + A.y * dy) * B.z;
        float l1 = (A.z * dx + A.w * dy) * B.z;
        float l2 = 1.0f - l0 - l1;
        float z  = l0 * B.w + l1 * z1v + l2 * z2v;
        if (l0 >= 0.0f && l1 >= 0.0f && l2 >= 0.0f && z > EPSF) {
            float u = l0 * u0 + l1 * u1 + l2 * u2;
            float v = l0 * v0 + l1 * v1 + l2 * v2;
            u = fminf(fmaxf(u, 0.0f), 1.0f);
            v = fminf(fmaxf(v, 0.0f), 1.0f);
            unsigned txi = (unsigned)(int)rintf(u * 511.0f);
            unsigned tyi = (unsigned)(int)rintf((1.0f - v) * 511.0f);
            unsigned long long key = tagbits
                | ((unsigned long long)(~__float_as_uint(z)) << 30)
                | ((unsigned long long)tyi << 9)
                | (unsigned long long)txi;
            atomicMax(&g_zbuf[yy * IMG + xx], key);
        }
    }
}

// ---------------------------------------------------------------------------
// Kernel 2: shade. One thread per pixel: 1 zbuf load (+ reset to 0) ->
// decode layer/texel -> 3 parallel texture loads -> store.
// ---------------------------------------------------------------------------
__global__ void __launch_bounds__(256)
shade_kernel(const float* __restrict__ tex,
             float* __restrict__ out) {
    int pid = blockIdx.x * blockDim.x + threadIdx.x;
    if (pid >= NPIX) return;

    unsigned long long key = g_zbuf[pid];
    g_zbuf[pid] = 0ull;                    // restore empty state for next call

    float c0 = 0.0f, c1 = 0.0f, c2 = 0.0f, hard = 0.0f;
    if (key != 0ull) {
        hard = 1.0f;
        int txi   = (int)(key & 511ull);
        int tyi   = (int)((key >> 9) & 511ull);
        int layer = (int)((key >> 18) & 3ull);
        const float* T = tex + layer * 3 * 512 * 512 + tyi * 512 + txi;
        c0 = T[0];
        c1 = T[262144];
        c2 = T[524288];
    }

    out[OFF_IM + pid * 3 + 0] = c0;
    out[OFF_IM + pid * 3 + 1] = c1;
    out[OFF_IM + pid * 3 + 2] = c2;
    out[OFF_PROB + pid] = hard;
    out[OFF_FG + pid]   = hard;
}

// ---------------------------------------------------------------------------
extern "C" void kernel_launch(void* const* d_in, const int* in_sizes, int n_in,
                              void* d_out, int out_size) {
    const float* points = (const float*)d_in[0];
    const float* camrot = (const float*)d_in[1];
    const float* campos = (const float*)d_in[2];
    const float* proj   = (const float*)d_in[3];
    const float* uv     = (const float*)d_in[4];
    const float* tex    = (const float*)d_in[5];
    const float* ts     = (const float*)d_in[6];
    const int*   faces  = (const int*)d_in[7];
    float* out = (float*)d_out;

    // 2 warps per (layer, face): 6144 warps = 196608 threads? No:
    // 6144 warps * 32 = 196608/..  6144*32 = 196,608? -> 6144 warps = 768 blocks of 8 warps.
    scatter_kernel<<<(NB * NF * 2 * 32 + 255) / 256, 256>>>(points, camrot,
                                                            campos, proj, faces,
                                                            uv, ts,
                                                            out + OFF_NORM);
    shade_kernel<<<NPIX / 256, 256>>>(tex, out);
}

// round 12
// speedup vs baseline: 1.4837x; 1.0226x over previous
#include <cuda_runtime.h>
#include <math.h>

#define EPSF 1e-8f
#define NB 3
#define NF 1024
#define NP 768
#define IMG 128
#define NPIX (IMG * IMG)

// out offsets (f32 elements)
#define OFF_IM     0
#define OFF_PROB   49152
#define OFF_NORM   65536
#define OFF_FG     74752

// Combined composite/z buffer, one u64 per pixel. 0 = empty (module-load
// default, restored by shade each call).
// key = rank<<62 | (~bits(z))<<30 | (1023-f)<<20 | layer<<18 | tyi<<9 | txi
//   atomicMax => max composite rank (last-drawn layer in ts order);
//   within a layer: min z, tie -> min face. Texel bits never affect order
//   (equal (layer,z,f,pixel) => equal texel coords).
static __device__ unsigned long long g_zbuf[NPIX];

__device__ __forceinline__ float pix_x(int x) {
    const float STEP = 2.0f / 127.0f;
    return (x == 127) ? 1.0f : (-1.0f + x * STEP);
}
__device__ __forceinline__ float pix_y(int y) {
    const float STEP = 2.0f / 127.0f;
    return (y == 127) ? -1.0f : (1.0f - y * STEP);
}

// stable argsort of -ts[:,2] over 3 layers; returns rank of layer l (0..2)
__device__ __forceinline__ int layer_rank(const float* ts, int l) {
    float k0 = -ts[2], k1 = -ts[5], k2 = -ts[8];
    int o0 = 0; float kv = k0;
    if (k1 < kv) { o0 = 1; kv = k1; }
    if (k2 < kv) { o0 = 2; kv = k2; }
    int r0i = (o0 == 0) ? 1 : 0;
    int r1i = (o0 == 2) ? 1 : 2;
    float kr0 = (r0i == 0) ? k0 : k1;
    float kr1 = (r1i == 1) ? k1 : k2;
    int o1, o2;
    if (kr0 <= kr1) { o1 = r0i; o2 = r1i; }
    else            { o1 = r1i; o2 = r0i; }
    return (l == o0) ? 0 : ((l == o1) ? 1 : 2);
}

// ---------------------------------------------------------------------------
// Kernel 1: prep + scatter. TWO warps per (layer, face) — interleaved halves
// of the flattened bbox sweep (halves the big-bbox tail).
// ---------------------------------------------------------------------------
__global__ void __launch_bounds__(256)
scatter_kernel(const float* __restrict__ pts,
               const float* __restrict__ camrot,
               const float* __restrict__ campos,
               const float* __restrict__ proj,
               const int*   __restrict__ faces,
               const float* __restrict__ uv,
               const float* __restrict__ ts,
               float* __restrict__ out_normals) {
    int w = (blockIdx.x * blockDim.x + threadIdx.x) >> 5;   // 0 .. 6143
    int lane = threadIdx.x & 31;
    int wg = w >> 1;            // (layer, face) id
    int half = w & 1;
    if (wg >= NB * NF) return;
    int l = wg >> 10;
    int f = wg & (NF - 1);

    int vis[3] = {faces[f * 3 + 0], faces[f * 3 + 1], faces[f * 3 + 2]};
    const float* R = camrot + l * 9;
    const float* C = campos + l * 3;
    float p0 = proj[0], p1 = proj[1];

    float vx[3], vy[3], vz[3], sx[3], sy[3];
#pragma unroll
    for (int k = 0; k < 3; k++) {
        const float* P = pts + (l * NP + vis[k]) * 3;
        float q0 = P[0] - C[0], q1 = P[1] - C[1], q2 = P[2] - C[2];
        float X = R[0] * q0 + R[1] * q1 + R[2] * q2;
        float Y = R[3] * q0 + R[4] * q1 + R[5] * q2;
        float Z = R[6] * q0 + R[7] * q1 + R[8] * q2;
        vx[k] = X; vy[k] = Y; vz[k] = Z;
        float zd = Z + EPSF;
        sx[k] = __fdiv_rn(X * p0, zd);
        sy[k] = __fdiv_rn(Y * p1, zd);
    }

    if (lane == 0 && half == 0) {
        float e1xx = vx[1] - vx[0], e1yy = vy[1] - vy[0], e1zz = vz[1] - vz[0];
        float e2xx = vx[2] - vx[0], e2yy = vy[2] - vy[0], e2zz = vz[2] - vz[0];
        float nx = e1yy * e2zz - e1zz * e2yy;
        float ny = e1zz * e2xx - e1xx * e2zz;
        float nz = e1xx * e2yy - e1yy * e2xx;
        float nn = __fsqrt_rn(nx * nx + ny * ny + nz * nz) + EPSF;
        float* on = out_normals + wg * 3;
        on[0] = __fdiv_rn(nx, nn);
        on[1] = __fdiv_rn(ny, nn);
        on[2] = __fdiv_rn(nz, nn);
    }

    float ax = sx[0], ay = sy[0], bx = sx[1], by = sy[1], cx = sx[2], cy = sy[2];
    float d = (by - cy) * (ax - cx) + (cx - bx) * (ay - cy);
    float zmax = fmaxf(vz[0], fmaxf(vz[1], vz[2]));
    bool valid = (fabsf(d) > EPSF) && (zmax > EPSF);
    if (!valid) return;

    float dn = d + EPSF;
    float rd = __frcp_rn(dn);
    float4 A = make_float4(by - cy, cx - bx, cy - ay, ax - cx);
    float4 B = make_float4(cx, cy, rd, vz[0]);
    float z1v = vz[1], z2v = vz[2];

    const float* U = uv + l * NP * 2;
    float u0 = U[2 * vis[0]],     u1 = U[2 * vis[1]],     u2 = U[2 * vis[2]];
    float v0 = U[2 * vis[0] + 1], v1 = U[2 * vis[1] + 1], v2 = U[2 * vis[2] + 1];

    const float STEP = 2.0f / 127.0f;
    float pad = 1.0f * STEP;
    float xmin = fminf(ax, fminf(bx, cx)) - pad;
    float xmax = fmaxf(ax, fmaxf(bx, cx)) + pad;
    float ymin = fminf(ay, fminf(by, cy)) - pad;
    float ymax = fmaxf(ay, fmaxf(by, cy)) + pad;

    const float INV_STEP = 63.5f;       // 1 / (2/127)
    int x0 = max(0, (int)floorf((xmin + 1.0f) * INV_STEP));
    int x1 = min(IMG - 1, (int)ceilf((xmax + 1.0f) * INV_STEP));
    int y0 = max(0, (int)floorf((1.0f - ymax) * INV_STEP));
    int y1 = min(IMG - 1, (int)ceilf((1.0f - ymin) * INV_STEP));
    if (x0 > x1 || y0 > y1) return;

    int wdt = x1 - x0 + 1;
    int total = wdt * (y1 - y0 + 1);

    unsigned long long rank = (unsigned long long)layer_rank(ts, l);
    unsigned long long tagbits = (rank << 62)
        | ((unsigned long long)(1023u - (unsigned)f) << 20)
        | ((unsigned long long)l << 18);

    for (int i = half * 32 + lane; i < total; i += 64) {
        int yy = y0 + i / wdt;
        int xx = x0 + i % wdt;
        float px = pix_x(xx), py = pix_y(yy);
        float dx = px - B.x, dy = py - B.y;
        float l0 = (A.x * dx + A.y * dy) * B.z;
        float l1 = (A.z * dx + A.w * dy) * B.z;
        float l2 = 1.0f - l0 - l1;
        float z  = l0 * B.w + l1 * z1v + l2 * z2v;
        if (l0 >= 0.0f && l1 >= 0.0f && l2 >= 0.0f && z > EPSF) {
            float u = l0 * u0 + l1 * u1 + l2 * u2;
            float v = l0 * v0 + l1 * v1 + l2 * v2;
            u = fminf(fmaxf(u, 0.0f), 1.0f);
            v = fminf(fmaxf(v, 0.0f), 1.0f);
            unsigned txi = (unsigned)(int)rintf(u * 511.0f);
            unsigned tyi = (unsigned)(int)rintf((1.0f - v) * 511.0f);
            unsigned long long key = tagbits
                | ((unsigned long long)(~__float_as_uint(z)) << 30)
                | ((unsigned long long)tyi << 9)
                | (unsigned long long)txi;
            atomicMax(&g_zbuf[yy * IMG + xx], key);
        }
    }
}

// ---------------------------------------------------------------------------
// Kernel 2: shade. One thread per (pixel, channel): 3 threads share one zbuf
// word (same sector -> merged load), each fetches ONE texel channel and makes
// ONE coalesced im write. Housekeeping spread: ch0 -> improb, ch1 -> fg,
// ch2 -> zbuf reset to 0 (empty state for the next graph replay).
// ---------------------------------------------------------------------------
__global__ void __launch_bounds__(256)
shade_kernel(const float* __restrict__ tex,
             float* __restrict__ out) {
    int tid = blockIdx.x * blockDim.x + threadIdx.x;
    if (tid >= NPIX * 3) return;
    int pid = tid / 3;
    int ch  = tid - pid * 3;

    unsigned long long key = g_zbuf[pid];

    float c = 0.0f, hard = 0.0f;
    if (key != 0ull) {
        hard = 1.0f;
        int txi   = (int)(key & 511ull);
        int tyi   = (int)((key >> 9) & 511ull);
        int layer = (int)((key >> 18) & 3ull);
        c = tex[layer * 3 * 512 * 512 + ch * 262144 + tyi * 512 + txi];
    }

    out[OFF_IM + tid] = c;                     // == out[OFF_IM + pid*3 + ch]
    if (ch == 0) out[OFF_PROB + pid] = hard;
    else if (ch == 1) out[OFF_FG + pid] = hard;
    else g_zbuf[pid] = 0ull;                   // restore empty state
}

// ---------------------------------------------------------------------------
extern "C" void kernel_launch(void* const* d_in, const int* in_sizes, int n_in,
                              void* d_out, int out_size) {
    const float* points = (const float*)d_in[0];
    const float* camrot = (const float*)d_in[1];
    const float* campos = (const float*)d_in[2];
    const float* proj   = (const float*)d_in[3];
    const float* uv     = (const float*)d_in[4];
    const float* tex    = (const float*)d_in[5];
    const float* ts     = (const float*)d_in[6];
    const int*   faces  = (const int*)d_in[7];
    float* out = (float*)d_out;

    // 6144 warps (2 per (layer,face)) = 768 blocks of 8 warps
    scatter_kernel<<<(NB * NF * 2 * 32) / 256, 256>>>(points, camrot, campos,
                                                      proj, faces, uv, ts,
                                                      out + OFF_NORM);
    shade_kernel<<<(NPIX * 3 + 255) / 256, 256>>>(tex, out);
}